// round 6
// baseline (speedup 1.0000x reference)
#include <cuda_runtime.h>
#include <cuda_fp16.h>
#include <mma.h>
#include <cstdint>

using namespace nvcuda;

#define BB 32
#define SS 2048
#define DD 1024
#define MM (BB * SS)

// ---------------- scratch (static device globals; no runtime alloc) ------
__device__ float  g_scores[BB * SS];
__device__ float  g_uq[BB * DD];
__device__ __half g_Whi[DD * DD];
__device__ __half g_Wlo[DD * DD];          // unscaled residual (subnormals ok)
__device__ __half g_Ahi[(size_t)MM * DD];
__device__ __half g_Alo[(size_t)MM * DD];

// ---------------- cp.async helpers ---------------------------------------
__device__ __forceinline__ uint32_t smem_u32(const void* p) {
    uint32_t a;
    asm("{ .reg .u64 t; cvta.to.shared.u64 t, %1; cvt.u32.u64 %0, t; }"
        : "=r"(a) : "l"(p));
    return a;
}
__device__ __forceinline__ void cp16(uint32_t dst, const void* src) {
    asm volatile("cp.async.cg.shared.global [%0], [%1], 16;" :: "r"(dst), "l"(src) : "memory");
}
__device__ __forceinline__ void cp_commit() {
    asm volatile("cp.async.commit_group;" ::: "memory");
}
template <int N> __device__ __forceinline__ void cp_wait() {
    asm volatile("cp.async.wait_group %0;" :: "n"(N) : "memory");
}

// ---------------- K_a: split W -> Whi/Wlo --------------------------------
__global__ void __launch_bounds__(256) wsplit_kernel(const float* __restrict__ W) {
    int i = (blockIdx.x * 256 + threadIdx.x) * 4;
    float4 v = *(const float4*)(W + i);
    __half2 h01 = __floats2half2_rn(v.x, v.y);
    __half2 h23 = __floats2half2_rn(v.z, v.w);
    float2 b01 = __half22float2(h01), b23 = __half22float2(h23);
    __half2 l01 = __floats2half2_rn(v.x - b01.x, v.y - b01.y);
    __half2 l23 = __floats2half2_rn(v.z - b23.x, v.w - b23.y);
    *(__half2*)(g_Whi + i)     = h01;
    *(__half2*)(g_Whi + i + 2) = h23;
    *(__half2*)(g_Wlo + i)     = l01;
    *(__half2*)(g_Wlo + i + 2) = l23;
}

// ---------------- K_a2: split h -> Ahi/Alo --------------------------------
__global__ void __launch_bounds__(256) asplit_kernel(const float* __restrict__ h) {
    size_t i = ((size_t)blockIdx.x * 256 + threadIdx.x) * 4;
    float4 v = *(const float4*)(h + i);
    __half2 h01 = __floats2half2_rn(v.x, v.y);
    __half2 h23 = __floats2half2_rn(v.z, v.w);
    float2 b01 = __half22float2(h01), b23 = __half22float2(h23);
    __half2 l01 = __floats2half2_rn(v.x - b01.x, v.y - b01.y);
    __half2 l23 = __floats2half2_rn(v.z - b23.x, v.w - b23.y);
    *(__half2*)(g_Ahi + i)     = h01;
    *(__half2*)(g_Ahi + i + 2) = h23;
    *(__half2*)(g_Alo + i)     = l01;
    *(__half2*)(g_Alo + i + 2) = l23;
}

// ---------------- K_b: uq = rs @ U^T; zero scores + matched --------------
__global__ void __launch_bounds__(256) init_kernel(const float* __restrict__ U,
                                                   const float* __restrict__ rs,
                                                   float* __restrict__ out) {
    int gtid = blockIdx.x * 256 + threadIdx.x;
    if (gtid < BB * SS) g_scores[gtid] = 0.0f;
    if (gtid < BB * DD) out[gtid] = 0.0f;

    int w = gtid >> 5;
    int lane = gtid & 31;
    if (w < BB * DD) {
        int b = w >> 10;
        int d = w & 1023;
        const float* Urow = U + (size_t)d * DD;
        const float* rb = rs + (size_t)b * DD;
        float acc = 0.0f;
        #pragma unroll 8
        for (int e = lane; e < DD; e += 32) acc += Urow[e] * rb[e];
        #pragma unroll
        for (int o = 16; o > 0; o >>= 1) acc += __shfl_xor_sync(0xffffffffu, acc, o);
        if (lane == 0) g_uq[w] = acc;
    }
}

// ---------------- K_c: 3-stage pipelined fp16x3 GEMM + relu + score ------
// 256 threads, block 128m x 128n, BK=64, 3-stage cp.async ring.
// 8 warps = 2(m) x 4(n); warp tile 64m x 32n.
// Inner loop is TERM-MAJOR: all hi*hi, then all hi*lo, then all lo*hi,
// so same-accumulator MMAs are 8 issues apart (no RAW chains).
#define LDH 72                    // halves; 144B row stride
#define TILE_B (128 * LDH * 2)    // 18432 B per array
#define STAGE_B (4 * TILE_B)      // Ahi|Alo|Bhi|Blo = 73728 B
#define NSTAGE 3
#define SMEM_DYN (NSTAGE * STAGE_B)   // 221184 B

__device__ __forceinline__ void load_stage(uint32_t st, int m0, int n0, int k0, int tid) {
    #pragma unroll
    for (int it = 0; it < 16; it++) {
        const int idx = tid + it * 256;
        const int arr = idx >> 10;          // compile-time constant per it
        const int rem = idx & 1023;
        const int row = rem >> 3;
        const int seg = rem & 7;
        const __half* src;
        if      (arr == 0) src = g_Ahi + (size_t)(m0 + row) * DD;
        else if (arr == 1) src = g_Alo + (size_t)(m0 + row) * DD;
        else if (arr == 2) src = g_Whi + (size_t)(n0 + row) * DD;
        else               src = g_Wlo + (size_t)(n0 + row) * DD;
        cp16(st + arr * TILE_B + row * (LDH * 2) + seg * 16, src + k0 + seg * 8);
    }
}

__global__ void __launch_bounds__(256, 1) gemm_score_kernel(const float* __restrict__ rs) {
    extern __shared__ __align__(16) unsigned char dyn[];
    __shared__ float uqs[128], qs[128];

    const int tid = threadIdx.x;
    const int wid = tid >> 5;
    const int wm  = wid & 1;     // 2 m-warps (64 rows)
    const int wn  = wid >> 1;    // 4 n-warps (32 cols)
    const int m0  = blockIdx.y * 128;
    const int n0  = blockIdx.x * 128;
    const int b   = blockIdx.y >> 4;

    if (tid < 128) {
        uqs[tid] = g_uq[b * DD + n0 + tid];
        qs[tid]  = rs[(size_t)b * DD + n0 + tid];
    }

    const uint32_t sbase = smem_u32(dyn);

    wmma::fragment<wmma::accumulator, 16, 16, 16, float> acc[4][2];
    #pragma unroll
    for (int i = 0; i < 4; i++)
        #pragma unroll
        for (int j = 0; j < 2; j++)
            wmma::fill_fragment(acc[i][j], 0.0f);

    load_stage(sbase, m0, n0, 0, tid);
    cp_commit();
    load_stage(sbase + STAGE_B, m0, n0, 64, tid);
    cp_commit();

    #pragma unroll 1
    for (int s = 0; s < 16; s++) {
        if (s < 15) cp_wait<1>(); else cp_wait<0>();
        __syncthreads();   // stage s ready; all warps done with buf (s+2)%3

        if (s + 2 < 16) {
            load_stage(sbase + ((s + 2) % NSTAGE) * STAGE_B, m0, n0, (s + 2) * 64, tid);
            cp_commit();
        }

        const __half* Ahi = (const __half*)(dyn + (s % NSTAGE) * STAGE_B);
        const __half* Bhi = Ahi + 2 * 128 * LDH;

        #pragma unroll
        for (int ks = 0; ks < 4; ks++) {
            wmma::fragment<wmma::matrix_a, 16, 16, 16, __half, wmma::row_major> ah[4], al[4];
            wmma::fragment<wmma::matrix_b, 16, 16, 16, __half, wmma::col_major> bh[2], bl[2];
            #pragma unroll
            for (int i = 0; i < 4; i++) {
                const __half* pa = Ahi + (wm * 64 + i * 16) * LDH + ks * 16;
                wmma::load_matrix_sync(ah[i], pa, LDH);
                wmma::load_matrix_sync(al[i], pa + 128 * LDH, LDH);
            }
            #pragma unroll
            for (int j = 0; j < 2; j++) {
                const __half* pb = Bhi + (wn * 32 + j * 16) * LDH + ks * 16;
                wmma::load_matrix_sync(bh[j], pb, LDH);
                wmma::load_matrix_sync(bl[j], pb + 128 * LDH, LDH);
            }
            // term-major: 8 independent MMAs per wave, chain distance 8
            #pragma unroll
            for (int i = 0; i < 4; i++)
                #pragma unroll
                for (int j = 0; j < 2; j++)
                    wmma::mma_sync(acc[i][j], ah[i], bh[j], acc[i][j]);  // hi*hi
            #pragma unroll
            for (int i = 0; i < 4; i++)
                #pragma unroll
                for (int j = 0; j < 2; j++)
                    wmma::mma_sync(acc[i][j], ah[i], bl[j], acc[i][j]);  // hi*lo
            #pragma unroll
            for (int i = 0; i < 4; i++)
                #pragma unroll
                for (int j = 0; j < 2; j++)
                    wmma::mma_sync(acc[i][j], al[i], bh[j], acc[i][j]);  // lo*hi
        }
    }
    __syncthreads();   // all mma reads done before aliasing smem as Es

    // epilogue: stage acc to smem, relu(+uq)*q, row-reduce, atomicAdd
    float* Es = (float*)dyn;    // 128 x 132 fp32
    #pragma unroll
    for (int i = 0; i < 4; i++)
        #pragma unroll
        for (int j = 0; j < 2; j++)
            wmma::store_matrix_sync(Es + (wm * 64 + i * 16) * 132 + (wn * 32 + j * 16),
                                    acc[i][j], 132, wmma::mem_row_major);
    __syncthreads();

    const int r  = tid >> 1;
    const int hh = tid & 1;
    float partial = 0.0f;
    #pragma unroll 16
    for (int c = hh * 64; c < hh * 64 + 64; c++) {
        float v = Es[r * 132 + c] + uqs[c];
        partial += fmaxf(v, 0.0f) * qs[c];
    }
    partial += __shfl_xor_sync(0xffffffffu, partial, 1);
    if (hh == 0) atomicAdd(&g_scores[m0 + r], partial);
}

// ---------------- K_d: softmax over S per batch ---------------------------
__global__ void __launch_bounds__(256) softmax_kernel(float* __restrict__ out) {
    const int b = blockIdx.x;
    const int tid = threadIdx.x;
    __shared__ float red[256];
    const float* sc = g_scores + (size_t)b * SS;
    float* wout = out + BB * DD + (size_t)b * SS;

    float mx = -1e30f;
    for (int i = tid; i < SS; i += 256) mx = fmaxf(mx, sc[i]);
    red[tid] = mx; __syncthreads();
    for (int s = 128; s > 0; s >>= 1) {
        if (tid < s) red[tid] = fmaxf(red[tid], red[tid + s]);
        __syncthreads();
    }
    mx = red[0]; __syncthreads();

    float sum = 0.0f;
    for (int i = tid; i < SS; i += 256) {
        float e = expf(sc[i] - mx);
        wout[i] = e;
        sum += e;
    }
    red[tid] = sum; __syncthreads();
    for (int s = 128; s > 0; s >>= 1) {
        if (tid < s) red[tid] += red[tid + s];
        __syncthreads();
    }
    float inv = 1.0f / red[0];
    for (int i = tid; i < SS; i += 256) wout[i] *= inv;
}

// ---------------- K_e: matched[b,d] += sum_{s chunk} h*w ------------------
__global__ void __launch_bounds__(256) matched_kernel(const float* __restrict__ h,
                                                      float* __restrict__ out) {
    const int b  = blockIdx.y;
    const int sc = blockIdx.z;
    const int d  = blockIdx.x * 256 + threadIdx.x;
    __shared__ float ws[256];
    const float* w = out + BB * DD + (size_t)b * SS + sc * 256;
    ws[threadIdx.x] = w[threadIdx.x];
    __syncthreads();

    const float* hb = h + ((size_t)b * SS + sc * 256) * DD + d;
    float acc = 0.0f;
    #pragma unroll 8
    for (int s = 0; s < 256; s++) acc += hb[(size_t)s * DD] * ws[s];
    atomicAdd(&out[(size_t)b * DD + d], acc);
}

// ---------------------------------------------------------------------------
extern "C" void kernel_launch(void* const* d_in, const int* in_sizes, int n_in,
                              void* d_out, int out_size) {
    const float* h  = (const float*)d_in[0];
    const float* rs = (const float*)d_in[1];
    const float* W  = (const float*)d_in[2];
    const float* U  = (const float*)d_in[3];
    float* out = (float*)d_out;

    cudaFuncSetAttribute(gemm_score_kernel,
                         cudaFuncAttributeMaxDynamicSharedMemorySize, SMEM_DYN);

    wsplit_kernel<<<1024, 256>>>(W);
    asplit_kernel<<<65536, 256>>>(h);
    init_kernel<<<4096, 256>>>(U, rs, out);
    gemm_score_kernel<<<dim3(8, 512), 256, SMEM_DYN>>>(rs);
    softmax_kernel<<<BB, 256>>>(out);
    matched_kernel<<<dim3(DD / 256, BB, 8), 256>>>(h, out);
}

// round 7
// speedup vs baseline: 1.0852x; 1.0852x over previous
#include <cuda_runtime.h>
#include <cuda_fp16.h>
#include <mma.h>
#include <cstdint>

using namespace nvcuda;

#define BB 32
#define SS 2048
#define DD 1024
#define MM (BB * SS)

// ---------------- scratch (static device globals; no runtime alloc) ------
__device__ float  g_scores[BB * SS];
__device__ float  g_uq[BB * DD];
__device__ __half g_Whi[DD * DD];
__device__ __half g_Wlo[DD * DD];          // unscaled residual (subnormals ok)
__device__ __half g_Ahi[(size_t)MM * DD];
__device__ __half g_Alo[(size_t)MM * DD];

// ---------------- cp.async helpers ---------------------------------------
__device__ __forceinline__ uint32_t smem_u32(const void* p) {
    uint32_t a;
    asm("{ .reg .u64 t; cvta.to.shared.u64 t, %1; cvt.u32.u64 %0, t; }"
        : "=r"(a) : "l"(p));
    return a;
}
__device__ __forceinline__ void cp16(uint32_t dst, const void* src) {
    asm volatile("cp.async.cg.shared.global [%0], [%1], 16;" :: "r"(dst), "l"(src) : "memory");
}
__device__ __forceinline__ void cp_commit() {
    asm volatile("cp.async.commit_group;" ::: "memory");
}
template <int N> __device__ __forceinline__ void cp_wait() {
    asm volatile("cp.async.wait_group %0;" :: "n"(N) : "memory");
}

// ---------------- K_a: split W -> Whi/Wlo --------------------------------
__global__ void __launch_bounds__(256) wsplit_kernel(const float* __restrict__ W) {
    int i = (blockIdx.x * 256 + threadIdx.x) * 4;
    float4 v = *(const float4*)(W + i);
    __half2 h01 = __floats2half2_rn(v.x, v.y);
    __half2 h23 = __floats2half2_rn(v.z, v.w);
    float2 b01 = __half22float2(h01), b23 = __half22float2(h23);
    __half2 l01 = __floats2half2_rn(v.x - b01.x, v.y - b01.y);
    __half2 l23 = __floats2half2_rn(v.z - b23.x, v.w - b23.y);
    *(__half2*)(g_Whi + i)     = h01;
    *(__half2*)(g_Whi + i + 2) = h23;
    *(__half2*)(g_Wlo + i)     = l01;
    *(__half2*)(g_Wlo + i + 2) = l23;
}

// ---------------- K_a2: split h -> Ahi/Alo --------------------------------
__global__ void __launch_bounds__(256) asplit_kernel(const float* __restrict__ h) {
    size_t i = ((size_t)blockIdx.x * 256 + threadIdx.x) * 4;
    float4 v = *(const float4*)(h + i);
    __half2 h01 = __floats2half2_rn(v.x, v.y);
    __half2 h23 = __floats2half2_rn(v.z, v.w);
    float2 b01 = __half22float2(h01), b23 = __half22float2(h23);
    __half2 l01 = __floats2half2_rn(v.x - b01.x, v.y - b01.y);
    __half2 l23 = __floats2half2_rn(v.z - b23.x, v.w - b23.y);
    *(__half2*)(g_Ahi + i)     = h01;
    *(__half2*)(g_Ahi + i + 2) = h23;
    *(__half2*)(g_Alo + i)     = l01;
    *(__half2*)(g_Alo + i + 2) = l23;
}

// ---------------- K_b: uq = rs @ U^T; zero scores + matched --------------
__global__ void __launch_bounds__(256) init_kernel(const float* __restrict__ U,
                                                   const float* __restrict__ rs,
                                                   float* __restrict__ out) {
    int gtid = blockIdx.x * 256 + threadIdx.x;
    if (gtid < BB * SS) g_scores[gtid] = 0.0f;
    if (gtid < BB * DD) out[gtid] = 0.0f;

    int w = gtid >> 5;
    int lane = gtid & 31;
    if (w < BB * DD) {
        int b = w >> 10;
        int d = w & 1023;
        const float* Urow = U + (size_t)d * DD;
        const float* rb = rs + (size_t)b * DD;
        float acc = 0.0f;
        #pragma unroll 8
        for (int e = lane; e < DD; e += 32) acc += Urow[e] * rb[e];
        #pragma unroll
        for (int o = 16; o > 0; o >>= 1) acc += __shfl_xor_sync(0xffffffffu, acc, o);
        if (lane == 0) g_uq[w] = acc;
    }
}

// ---------------- K_c: fp16x3 GEMM + relu + score ------------------------
// Block tile 256m x 128n, BK=64, double-buffered cp.async.
// 8 warps = 4(m) x 2(n); warp tile 64m x 64n (LDSM/mma ratio 0.33).
#define LDH 72                    // halves; 144B row stride
#define A_TILE_B (256 * LDH * 2)  // 36864 B per A array
#define B_TILE_B (128 * LDH * 2)  // 18432 B per B array
#define STAGE_B (2 * A_TILE_B + 2 * B_TILE_B)   // 110592 B
#define SMEM_DYN (2 * STAGE_B)                  // 221184 B

__device__ __forceinline__ void load_stage(uint32_t st, int m0, int n0, int k0, int tid) {
    // Ahi: its 0-7 | Alo: 8-15 | Bhi: 16-19 | Blo: 20-23   (24 x 256 = 6144 xfers)
    #pragma unroll
    for (int it = 0; it < 24; it++) {
        const int idx = tid + it * 256;
        const __half* src;
        uint32_t dst;
        if (it < 16) {
            const int rem = idx & 2047;         // A: 256 rows x 8 segs
            const int row = rem >> 3;
            const int seg = rem & 7;
            src = (it < 8 ? g_Ahi : g_Alo) + (size_t)(m0 + row) * DD + k0 + seg * 8;
            dst = st + (it < 8 ? 0 : A_TILE_B) + row * (LDH * 2) + seg * 16;
        } else {
            const int rem = idx & 1023;         // B: 128 rows x 8 segs
            const int row = rem >> 3;
            const int seg = rem & 7;
            src = (it < 20 ? g_Whi : g_Wlo) + (size_t)(n0 + row) * DD + k0 + seg * 8;
            dst = st + 2 * A_TILE_B + (it < 20 ? 0 : B_TILE_B) + row * (LDH * 2) + seg * 16;
        }
        cp16(dst, src);
    }
}

__global__ void __launch_bounds__(256, 1) gemm_score_kernel(const float* __restrict__ rs) {
    extern __shared__ __align__(16) unsigned char dyn[];
    __shared__ float uqs[128], qs[128];

    const int tid = threadIdx.x;
    const int wid = tid >> 5;
    const int wm  = wid & 3;     // 4 m-warps (64 rows each)
    const int wn  = wid >> 2;    // 2 n-warps (64 cols each)
    const int m0  = blockIdx.y * 256;
    const int n0  = blockIdx.x * 128;
    const int b   = blockIdx.y >> 3;   // 8 m-blocks per batch (2048/256)

    if (tid < 128) {
        uqs[tid] = g_uq[b * DD + n0 + tid];
        qs[tid]  = rs[(size_t)b * DD + n0 + tid];
    }

    const uint32_t sbase = smem_u32(dyn);

    wmma::fragment<wmma::accumulator, 16, 16, 16, float> acc[4][4];
    #pragma unroll
    for (int i = 0; i < 4; i++)
        #pragma unroll
        for (int j = 0; j < 4; j++)
            wmma::fill_fragment(acc[i][j], 0.0f);

    load_stage(sbase, m0, n0, 0, tid);
    cp_commit();

    #pragma unroll 1
    for (int s = 0; s < 16; s++) {
        if (s + 1 < 16) {
            load_stage(sbase + ((s + 1) & 1) * STAGE_B, m0, n0, (s + 1) * 64, tid);
            cp_commit();
            cp_wait<1>();
        } else {
            cp_wait<0>();
        }
        __syncthreads();

        const __half* Ahi = (const __half*)(dyn + (s & 1) * STAGE_B);
        const __half* Bhi = Ahi + 2 * 256 * LDH;

        #pragma unroll
        for (int ks = 0; ks < 4; ks++) {
            wmma::fragment<wmma::matrix_a, 16, 16, 16, __half, wmma::row_major> ah[4], al[4];
            #pragma unroll
            for (int i = 0; i < 4; i++) {
                const __half* pa = Ahi + (wm * 64 + i * 16) * LDH + ks * 16;
                wmma::load_matrix_sync(ah[i], pa, LDH);
                wmma::load_matrix_sync(al[i], pa + 256 * LDH, LDH);
            }
            #pragma unroll
            for (int j = 0; j < 4; j++) {
                wmma::fragment<wmma::matrix_b, 16, 16, 16, __half, wmma::col_major> bh, bl;
                const __half* pb = Bhi + (wn * 64 + j * 16) * LDH + ks * 16;
                wmma::load_matrix_sync(bh, pb, LDH);
                wmma::load_matrix_sync(bl, pb + 128 * LDH, LDH);
                #pragma unroll
                for (int i = 0; i < 4; i++)
                    wmma::mma_sync(acc[i][j], ah[i], bh, acc[i][j]);   // hi*hi
                #pragma unroll
                for (int i = 0; i < 4; i++)
                    wmma::mma_sync(acc[i][j], ah[i], bl, acc[i][j]);   // hi*lo
                #pragma unroll
                for (int i = 0; i < 4; i++)
                    wmma::mma_sync(acc[i][j], al[i], bh, acc[i][j]);   // lo*hi
            }
        }
        __syncthreads();   // all reads done before buffer refill / aliasing
    }

    // epilogue: stage acc to smem, relu(+uq)*q, row-reduce, atomicAdd
    float* Es = (float*)dyn;    // 256 x 132 fp32 = 135168 B
    #pragma unroll
    for (int i = 0; i < 4; i++)
        #pragma unroll
        for (int j = 0; j < 4; j++)
            wmma::store_matrix_sync(Es + (wm * 64 + i * 16) * 132 + (wn * 64 + j * 16),
                                    acc[i][j], 132, wmma::mem_row_major);
    __syncthreads();

    // 256 threads, one row each, 128 cols
    float partial = 0.0f;
    const float* row = Es + tid * 132;
    #pragma unroll 16
    for (int c = 0; c < 128; c++) {
        float v = row[c] + uqs[c];
        partial += fmaxf(v, 0.0f) * qs[c];
    }
    atomicAdd(&g_scores[m0 + tid], partial);
}

// ---------------- K_d: softmax over S per batch ---------------------------
__global__ void __launch_bounds__(256) softmax_kernel(float* __restrict__ out) {
    const int b = blockIdx.x;
    const int tid = threadIdx.x;
    __shared__ float red[256];
    const float* sc = g_scores + (size_t)b * SS;
    float* wout = out + BB * DD + (size_t)b * SS;

    float mx = -1e30f;
    for (int i = tid; i < SS; i += 256) mx = fmaxf(mx, sc[i]);
    red[tid] = mx; __syncthreads();
    for (int s = 128; s > 0; s >>= 1) {
        if (tid < s) red[tid] = fmaxf(red[tid], red[tid + s]);
        __syncthreads();
    }
    mx = red[0]; __syncthreads();

    float sum = 0.0f;
    for (int i = tid; i < SS; i += 256) {
        float e = expf(sc[i] - mx);
        wout[i] = e;
        sum += e;
    }
    red[tid] = sum; __syncthreads();
    for (int s = 128; s > 0; s >>= 1) {
        if (tid < s) red[tid] += red[tid + s];
        __syncthreads();
    }
    float inv = 1.0f / red[0];
    for (int i = tid; i < SS; i += 256) wout[i] *= inv;
}

// ---------------- K_e: matched[b,d] += sum_{s chunk} h*w ------------------
__global__ void __launch_bounds__(256) matched_kernel(const float* __restrict__ h,
                                                      float* __restrict__ out) {
    const int b  = blockIdx.y;
    const int sc = blockIdx.z;
    const int d  = blockIdx.x * 256 + threadIdx.x;
    __shared__ float ws[256];
    const float* w = out + BB * DD + (size_t)b * SS + sc * 256;
    ws[threadIdx.x] = w[threadIdx.x];
    __syncthreads();

    const float* hb = h + ((size_t)b * SS + sc * 256) * DD + d;
    float acc = 0.0f;
    #pragma unroll 8
    for (int s = 0; s < 256; s++) acc += hb[(size_t)s * DD] * ws[s];
    atomicAdd(&out[(size_t)b * DD + d], acc);
}

// ---------------------------------------------------------------------------
extern "C" void kernel_launch(void* const* d_in, const int* in_sizes, int n_in,
                              void* d_out, int out_size) {
    const float* h  = (const float*)d_in[0];
    const float* rs = (const float*)d_in[1];
    const float* W  = (const float*)d_in[2];
    const float* U  = (const float*)d_in[3];
    float* out = (float*)d_out;

    cudaFuncSetAttribute(gemm_score_kernel,
                         cudaFuncAttributeMaxDynamicSharedMemorySize, SMEM_DYN);

    wsplit_kernel<<<1024, 256>>>(W);
    asplit_kernel<<<65536, 256>>>(h);
    init_kernel<<<4096, 256>>>(U, rs, out);
    gemm_score_kernel<<<dim3(8, 256), 256, SMEM_DYN>>>(rs);
    softmax_kernel<<<BB, 256>>>(out);
    matched_kernel<<<dim3(DD / 256, BB, 8), 256>>>(h, out);
}